// round 5
// baseline (speedup 1.0000x reference)
#include <cuda_runtime.h>
#include <math.h>

#define VOCAB 10000

// ---------------- scratch (static device globals; no allocation) ----------------
static __device__ float    g_Gx[4096 * 1024];   // input-proj gates [row=b*64+t][1024]
static __device__ float    g_H[64 * 256];       // current hidden state [b][h]
static __device__ float    g_hs[4096 * 256];    // all hidden states [row][h]
static __device__ unsigned g_bar[64];           // per-step grid barrier counters
static __device__ float    g_pmax[79 * 4096];   // softmax partial max   [tile][row]
static __device__ float    g_psum[79 * 4096];   // softmax partial sumexp[tile][row]
static __device__ float    g_lt[4096];          // target logit per row

__device__ __forceinline__ float sigm(float x) { return 1.0f / (1.0f + expf(-x)); }

// ---------------- init: zero h0 and barrier counters (every launch) ----------------
__global__ void k_init()
{
    int t = blockIdx.x * blockDim.x + threadIdx.x;
    if (t < 64 * 256) g_H[t] = 0.0f;
    if (t < 64) g_bar[t] = 0u;
}

// ---------------- kA: embedding gather + X @ Wx + b -> g_Gx ----------------
// 128x128 tile, K=256, 8x8 micro, conflict-free frags, reg double-buffer.
// grid (8 col-tiles, 32 row-tiles)
__global__ void __launch_bounds__(256) kA(const int* __restrict__ idx,
                                          const float* __restrict__ E,
                                          const float* __restrict__ W,   // [512][1024]
                                          const float* __restrict__ bl)
{
    __shared__ float sm[4224];
    float* As = sm;            // [16][132] transposed: As[k][row]
    float* Bs = sm + 2112;     // [16][132]
    const int tid = threadIdx.x;
    const int tx = tid & 15, ty = tid >> 4;
    const int ro = blockIdx.y << 7;
    const int co = blockIdx.x << 7;

    const int lrow = tid >> 1;           // A-load row 0..127
    const int lkb  = (tid & 1) << 3;     // A-load k base 0/8
    const int erow = idx[ro + lrow];
    const int bk   = tid >> 4;           // B-load k 0..15
    const int bcb  = (tid & 15) << 3;    // B-load col base

    float acc[8][8] = {};
    float4 na0, na1, nb0, nb1;

    // prefetch tile 0
    {
        const float* sa = E + erow * 256 + lkb;
        na0 = *(const float4*)sa; na1 = *(const float4*)(sa + 4);
        const float* sb = W + bk * 1024 + co + bcb;
        nb0 = *(const float4*)sb; nb1 = *(const float4*)(sb + 4);
    }

    for (int kt = 0; kt < 16; kt++) {
        __syncthreads();
        {   // store prefetched regs -> smem (A transposed)
            float* d = As + lrow;
            d[(lkb + 0) * 132] = na0.x; d[(lkb + 1) * 132] = na0.y;
            d[(lkb + 2) * 132] = na0.z; d[(lkb + 3) * 132] = na0.w;
            d[(lkb + 4) * 132] = na1.x; d[(lkb + 5) * 132] = na1.y;
            d[(lkb + 6) * 132] = na1.z; d[(lkb + 7) * 132] = na1.w;
            float* db = Bs + bk * 132 + bcb;
            *(float4*)db = nb0; *(float4*)(db + 4) = nb1;
        }
        __syncthreads();
        if (kt < 15) {
            int k0 = (kt + 1) << 4;
            const float* sa = E + erow * 256 + k0 + lkb;
            na0 = *(const float4*)sa; na1 = *(const float4*)(sa + 4);
            const float* sb = W + (k0 + bk) * 1024 + co + bcb;
            nb0 = *(const float4*)sb; nb1 = *(const float4*)(sb + 4);
        }
#pragma unroll
        for (int k = 0; k < 16; k++) {
            float4 a0 = *(const float4*)(As + k * 132 + (ty << 3));
            float4 a1 = *(const float4*)(As + k * 132 + (ty << 3) + 4);
            float4 b0 = *(const float4*)(Bs + k * 132 + (tx << 2));        // cols tx*4..+3
            float4 b1 = *(const float4*)(Bs + k * 132 + 64 + (tx << 2));   // cols 64+tx*4..+3
            float a[8] = {a0.x, a0.y, a0.z, a0.w, a1.x, a1.y, a1.z, a1.w};
            float b[8] = {b0.x, b0.y, b0.z, b0.w, b1.x, b1.y, b1.z, b1.w};
#pragma unroll
            for (int i = 0; i < 8; i++)
#pragma unroll
                for (int j = 0; j < 8; j++)
                    acc[i][j] = fmaf(a[i], b[j], acc[i][j]);
        }
    }

    float bias[8];
#pragma unroll
    for (int j = 0; j < 8; j++) {
        int gc = co + ((j < 4) ? ((tx << 2) + j) : (64 + (tx << 2) + j - 4));
        bias[j] = bl[gc];
    }
#pragma unroll
    for (int i = 0; i < 8; i++) {
        int r = ro + (ty << 3) + i;
        float* dst0 = &g_Gx[r * 1024 + co + (tx << 2)];
        float4 v0 = {acc[i][0] + bias[0], acc[i][1] + bias[1],
                     acc[i][2] + bias[2], acc[i][3] + bias[3]};
        float4 v1 = {acc[i][4] + bias[4], acc[i][5] + bias[5],
                     acc[i][6] + bias[6], acc[i][7] + bias[7]};
        *(float4*)dst0 = v0;
        *(float4*)(dst0 + 64) = v1;
    }
}

// ---------------- kB: persistent LSTM recurrence ----------------
// 128 CTAs = 8 batch-groups x 16 hid-groups. Each CTA: 8 batches x 32 col-pairs.
// k-split WITHIN warp (kq = tid&7) -> partial reduce via shfl, no smem partials.
__global__ void __launch_bounds__(256) kB(const float* __restrict__ W)   // W_lstm
{
    __shared__ float s_h[8 * 256];       // staged h for this CTA's 8 batches
    __shared__ float s_g[8 * 64];        // reduced gate sums [b][lc]

    const int tid = threadIdx.x;
    const int bg = blockIdx.x >> 4;      // 0..7
    const int hg = blockIdx.x & 15;      // 0..15
    const int B0 = bg << 3;

    const int kq = tid & 7;              // k-split within warp
    const int cg = tid >> 3;             // col pair 0..31
    const int lc0 = cg << 1;
    const int gc0 = ((lc0 >> 4) << 8) + (hg << 4) + (lc0 & 15);  // global gate col

    float w0[32], w1[32];
#pragma unroll
    for (int kk = 0; kk < 32; kk++) {
        const float* wr = W + (256 + (kq << 5) + kk) * 1024 + gc0;
        w0[kk] = wr[0];
        w1[kk] = wr[1];
    }

    const int rb = tid >> 4, rh = tid & 15;   // pointwise identity (tid<128)
    const int ghid = (hg << 4) + rh;
    float c_state = 0.0f;

    for (int t = 0; t < 64; t++) {
        // stage h[8 batches][256] into smem
#pragma unroll
        for (int v = 0; v < 2; v++) {
            int li = tid + (v << 8);          // float4 slot 0..511
            int b = li >> 6, k4 = li & 63;
            ((float4*)s_h)[(b << 6) + k4] = ((const float4*)g_H)[((B0 + b) << 6) + k4];
        }
        __syncthreads();

        float acc0[8], acc1[8];
#pragma unroll
        for (int b = 0; b < 8; b++) {
            const float4* hp = (const float4*)(s_h + (b << 8) + (kq << 5));
            float a0 = 0.0f, a1 = 0.0f;
#pragma unroll
            for (int q = 0; q < 8; q++) {
                float4 h4 = hp[q];
                a0 = fmaf(h4.x, w0[4 * q + 0], a0); a1 = fmaf(h4.x, w1[4 * q + 0], a1);
                a0 = fmaf(h4.y, w0[4 * q + 1], a0); a1 = fmaf(h4.y, w1[4 * q + 1], a1);
                a0 = fmaf(h4.z, w0[4 * q + 2], a0); a1 = fmaf(h4.z, w1[4 * q + 2], a1);
                a0 = fmaf(h4.w, w0[4 * q + 3], a0); a1 = fmaf(h4.w, w1[4 * q + 3], a1);
            }
            acc0[b] = a0; acc1[b] = a1;
        }
        // reduce across the 8 k-split lanes (shuffle tree)
#pragma unroll
        for (int mask = 1; mask < 8; mask <<= 1) {
#pragma unroll
            for (int b = 0; b < 8; b++) {
                acc0[b] += __shfl_xor_sync(0xFFFFFFFFu, acc0[b], mask);
                acc1[b] += __shfl_xor_sync(0xFFFFFFFFu, acc1[b], mask);
            }
        }
        if (kq == 0) {
#pragma unroll
            for (int b = 0; b < 8; b++) {
                float2 v = {acc0[b], acc1[b]};
                *(float2*)&s_g[(b << 6) + lc0] = v;
            }
        }
        __syncthreads();

        if (tid < 128) {
            const float* gx = g_Gx + (((B0 + rb) << 6) + t) * 1024 + ghid;
            float vi = s_g[(rb << 6) + rh]      + gx[0];
            float vj = s_g[(rb << 6) + 16 + rh] + gx[256];
            float vf = s_g[(rb << 6) + 32 + rh] + gx[512];
            float vo = s_g[(rb << 6) + 48 + rh] + gx[768];
            c_state = sigm(vf + 1.0f) * c_state + sigm(vi) * tanhf(vj);
            float h = sigm(vo) * tanhf(c_state);
            g_H[((B0 + rb) << 8) + ghid] = h;
            g_hs[(((B0 + rb) << 6) + t) * 256 + ghid] = h;
        }

        if (t < 63) {   // grid barrier between steps
            __threadfence();
            __syncthreads();
            if (tid == 0) {
                atomicAdd(&g_bar[t], 1u);
                volatile unsigned* p = &g_bar[t];
                while (*p < 128u) { }
                __threadfence();
            }
            __syncthreads();
        } else {
            __syncthreads();
        }
    }
}

// ---------------- kC: hs @ W_dense + b, fused online-softmax partials ----------------
// grid (79 col-tiles, 32 row-tiles), 128x128 tile, K=256, 8x8 micro,
// conflict-free frags (cols split tx*4 / 64+tx*4), reg double-buffer.
__global__ void __launch_bounds__(256) kC(const float* __restrict__ Wd,
                                          const float* __restrict__ bd,
                                          const int* __restrict__ tgt)
{
    __shared__ float sm[4224];           // As[16][132] + Bs[16][132] | red reuse
    float* As = sm;
    float* Bs = sm + 2112;
    const int tid = threadIdx.x;
    const int tx = tid & 15, ty = tid >> 4;
    const int ro = blockIdx.y << 7;
    const int co = blockIdx.x << 7;

    const int lrow = tid >> 1;
    const int lkb  = (tid & 1) << 3;
    const int bk   = tid >> 4;
    const int bcb  = (tid & 15) << 3;
    const bool tail = (co + 128 > VOCAB);

    float acc[8][8] = {};
    float4 na0, na1, nb0, nb1;

    // prefetch tile 0
    {
        const float* sa = g_hs + (ro + lrow) * 256 + lkb;
        na0 = *(const float4*)sa; na1 = *(const float4*)(sa + 4);
        const float* sb = Wd + bk * VOCAB + co + bcb;
        if (!tail) {
            nb0 = *(const float4*)sb; nb1 = *(const float4*)(sb + 4);
        } else {
            float e[8];
#pragma unroll
            for (int q = 0; q < 8; q++) e[q] = (co + bcb + q < VOCAB) ? sb[q] : 0.0f;
            nb0 = {e[0], e[1], e[2], e[3]}; nb1 = {e[4], e[5], e[6], e[7]};
        }
    }

    for (int kt = 0; kt < 16; kt++) {
        __syncthreads();
        {
            float* d = As + lrow;
            d[(lkb + 0) * 132] = na0.x; d[(lkb + 1) * 132] = na0.y;
            d[(lkb + 2) * 132] = na0.z; d[(lkb + 3) * 132] = na0.w;
            d[(lkb + 4) * 132] = na1.x; d[(lkb + 5) * 132] = na1.y;
            d[(lkb + 6) * 132] = na1.z; d[(lkb + 7) * 132] = na1.w;
            float* db = Bs + bk * 132 + bcb;
            *(float4*)db = nb0; *(float4*)(db + 4) = nb1;
        }
        __syncthreads();
        if (kt < 15) {
            int k0 = (kt + 1) << 4;
            const float* sa = g_hs + (ro + lrow) * 256 + k0 + lkb;
            na0 = *(const float4*)sa; na1 = *(const float4*)(sa + 4);
            const float* sb = Wd + (k0 + bk) * VOCAB + co + bcb;
            if (!tail) {
                nb0 = *(const float4*)sb; nb1 = *(const float4*)(sb + 4);
            } else {
                float e[8];
#pragma unroll
                for (int q = 0; q < 8; q++) e[q] = (co + bcb + q < VOCAB) ? sb[q] : 0.0f;
                nb0 = {e[0], e[1], e[2], e[3]}; nb1 = {e[4], e[5], e[6], e[7]};
            }
        }
#pragma unroll
        for (int k = 0; k < 16; k++) {
            float4 a0 = *(const float4*)(As + k * 132 + (ty << 3));
            float4 a1 = *(const float4*)(As + k * 132 + (ty << 3) + 4);
            float4 b0 = *(const float4*)(Bs + k * 132 + (tx << 2));
            float4 b1 = *(const float4*)(Bs + k * 132 + 64 + (tx << 2));
            float a[8] = {a0.x, a0.y, a0.z, a0.w, a1.x, a1.y, a1.z, a1.w};
            float b[8] = {b0.x, b0.y, b0.z, b0.w, b1.x, b1.y, b1.z, b1.w};
#pragma unroll
            for (int i = 0; i < 8; i++)
#pragma unroll
                for (int j = 0; j < 8; j++)
                    acc[i][j] = fmaf(a[i], b[j], acc[i][j]);
        }
    }

    // epilogue: bias, target-logit capture, per-thread row max/sumexp
    int   gcol[8];
    float bias[8];
    bool  valid[8];
#pragma unroll
    for (int j = 0; j < 8; j++) {
        int gc = co + ((j < 4) ? ((tx << 2) + j) : (64 + (tx << 2) + j - 4));
        gcol[j] = gc;
        valid[j] = (gc < VOCAB);
        bias[j] = valid[j] ? bd[gc] : 0.0f;
    }
    float m[8], s[8];
#pragma unroll
    for (int i = 0; i < 8; i++) {
        int gr = ro + (ty << 3) + i;
        int tg = tgt[gr];
        float mi = -1e30f;
#pragma unroll
        for (int j = 0; j < 8; j++) {
            float l = valid[j] ? (acc[i][j] + bias[j]) : -1e30f;
            acc[i][j] = l;
            if (valid[j] && gcol[j] == tg) g_lt[gr] = l;
            mi = fmaxf(mi, l);
        }
        float si = 0.0f;
#pragma unroll
        for (int j = 0; j < 8; j++) si += __expf(acc[i][j] - mi);
        m[i] = mi; s[i] = si;
    }

    __syncthreads();   // reuse smem for reduction
    float* redm = sm;          // [128][16]
    float* reds = sm + 2048;   // [128][16]
#pragma unroll
    for (int i = 0; i < 8; i++) {
        redm[((ty << 3) + i) * 16 + tx] = m[i];
        reds[((ty << 3) + i) * 16 + tx] = s[i];
    }
    __syncthreads();
    if (tid < 128) {
        float M = -1e30f;
#pragma unroll
        for (int x = 0; x < 16; x++) M = fmaxf(M, redm[tid * 16 + x]);
        float S = 0.0f;
#pragma unroll
        for (int x = 0; x < 16; x++) S += reds[tid * 16 + x] * __expf(redm[tid * 16 + x] - M);
        g_pmax[blockIdx.x * 4096 + ro + tid] = M;
        g_psum[blockIdx.x * 4096 + ro + tid] = S;
    }
}

// ---------------- kD: combine partials -> perplexity ----------------
__global__ void kD(float* __restrict__ out)
{
    int r = blockIdx.x * 128 + threadIdx.x;   // = b*64 + t, matches out[b][t]
    float M = g_pmax[r];
    float S = g_psum[r];
    for (int i = 1; i < 79; i++) {
        float mi = g_pmax[i * 4096 + r];
        float si = g_psum[i * 4096 + r];
        float nm = fmaxf(M, mi);
        S = S * __expf(M - nm) + si * __expf(mi - nm);
        M = nm;
    }
    out[r] = S * __expf(M - g_lt[r]);   // ppl = sumexp * exp(max - target_logit)
}

// ---------------- launch ----------------
extern "C" void kernel_launch(void* const* d_in, const int* in_sizes, int n_in,
                              void* d_out, int out_size)
{
    const int*   input_data = (const int*)d_in[0];
    const int*   targets    = (const int*)d_in[1];
    const float* E          = (const float*)d_in[2];
    const float* W_lstm     = (const float*)d_in[3];
    const float* b_lstm     = (const float*)d_in[4];
    const float* W_dense    = (const float*)d_in[5];
    const float* b_dense    = (const float*)d_in[6];
    float* out = (float*)d_out;
    (void)in_sizes; (void)n_in; (void)out_size;

    k_init<<<64, 256>>>();
    kA<<<dim3(8, 32), 256>>>(input_data, E, W_lstm, b_lstm);
    kB<<<128, 256>>>(W_lstm);
    kC<<<dim3(79, 32), 256>>>(W_dense, b_dense, targets);
    kD<<<32, 128>>>(out);
}

// round 6
// speedup vs baseline: 1.4819x; 1.4819x over previous
#include <cuda_runtime.h>
#include <math.h>

#define VOCAB 10000
typedef unsigned long long ull;

// packed f32x2 FMA: d = a*b + d (elementwise on the two packed floats)
#define FMA2(d, a, b) asm("fma.rn.f32x2 %0, %1, %2, %0;" : "+l"(d) : "l"(a), "l"(b))
#define UNPK2(lo, hi, v) do { unsigned _ulo, _uhi; \
    asm("mov.b64 {%0,%1}, %2;" : "=r"(_ulo), "=r"(_uhi) : "l"(v)); \
    lo = __uint_as_float(_ulo); hi = __uint_as_float(_uhi); } while (0)

// ---------------- scratch (static device globals; no allocation) ----------------
static __device__ float    g_Gx[4096 * 1024];   // input-proj gates [row=b*64+t][1024]
static __device__ float    g_H[64 * 256];       // current hidden state [b][h]
static __device__ float    g_hs[4096 * 256];    // all hidden states [row][h]
static __device__ unsigned g_bar[64];           // per-step grid barrier counters
static __device__ float    g_pmax[79 * 4096];   // softmax partial max   [tile][row]
static __device__ float    g_psum[79 * 4096];   // softmax partial sumexp[tile][row]
static __device__ float    g_lt[4096];          // target logit per row

__device__ __forceinline__ float sigm(float x) { return 1.0f / (1.0f + __expf(-x)); }

// ---------------- init ----------------
__global__ void k_init()
{
    int t = blockIdx.x * blockDim.x + threadIdx.x;
    if (t < 64 * 256) g_H[t] = 0.0f;
    if (t < 64) g_bar[t] = 0u;
}

// ---------------- kA: embedding gather + X @ Wx + b -> g_Gx ----------------
// 128x128 tile, K=256, 8x8 micro, conflict-free frags, reg double-buffer.
__global__ void __launch_bounds__(256) kA(const int* __restrict__ idx,
                                          const float* __restrict__ E,
                                          const float* __restrict__ W,   // [512][1024]
                                          const float* __restrict__ bl)
{
    __shared__ __align__(16) float sm[4224];
    float* As = sm;            // [16][132] transposed: As[k][row]
    float* Bs = sm + 2112;     // [16][132]
    const int tid = threadIdx.x;
    const int tx = tid & 15, ty = tid >> 4;
    const int ro = blockIdx.y << 7;
    const int co = blockIdx.x << 7;

    const int lrow = tid >> 1;
    const int lkb  = (tid & 1) << 3;
    const int erow = idx[ro + lrow];
    const int bk   = tid >> 4;
    const int bcb  = (tid & 15) << 3;

    float acc[8][8] = {};
    float4 na0, na1, nb0, nb1;

    {
        const float* sa = E + erow * 256 + lkb;
        na0 = *(const float4*)sa; na1 = *(const float4*)(sa + 4);
        const float* sb = W + bk * 1024 + co + bcb;
        nb0 = *(const float4*)sb; nb1 = *(const float4*)(sb + 4);
    }

    for (int kt = 0; kt < 16; kt++) {
        __syncthreads();
        {
            float* d = As + lrow;
            d[(lkb + 0) * 132] = na0.x; d[(lkb + 1) * 132] = na0.y;
            d[(lkb + 2) * 132] = na0.z; d[(lkb + 3) * 132] = na0.w;
            d[(lkb + 4) * 132] = na1.x; d[(lkb + 5) * 132] = na1.y;
            d[(lkb + 6) * 132] = na1.z; d[(lkb + 7) * 132] = na1.w;
            float* db = Bs + bk * 132 + bcb;
            *(float4*)db = nb0; *(float4*)(db + 4) = nb1;
        }
        __syncthreads();
        if (kt < 15) {
            int k0 = (kt + 1) << 4;
            const float* sa = E + erow * 256 + k0 + lkb;
            na0 = *(const float4*)sa; na1 = *(const float4*)(sa + 4);
            const float* sb = W + (k0 + bk) * 1024 + co + bcb;
            nb0 = *(const float4*)sb; nb1 = *(const float4*)(sb + 4);
        }
#pragma unroll
        for (int k = 0; k < 16; k++) {
            float4 a0 = *(const float4*)(As + k * 132 + (ty << 3));
            float4 a1 = *(const float4*)(As + k * 132 + (ty << 3) + 4);
            float4 b0 = *(const float4*)(Bs + k * 132 + (tx << 2));
            float4 b1 = *(const float4*)(Bs + k * 132 + 64 + (tx << 2));
            float a[8] = {a0.x, a0.y, a0.z, a0.w, a1.x, a1.y, a1.z, a1.w};
            float b[8] = {b0.x, b0.y, b0.z, b0.w, b1.x, b1.y, b1.z, b1.w};
#pragma unroll
            for (int i = 0; i < 8; i++)
#pragma unroll
                for (int j = 0; j < 8; j++)
                    acc[i][j] = fmaf(a[i], b[j], acc[i][j]);
        }
    }

    float bias[8];
#pragma unroll
    for (int j = 0; j < 8; j++) {
        int gc = co + ((j < 4) ? ((tx << 2) + j) : (64 + (tx << 2) + j - 4));
        bias[j] = bl[gc];
    }
#pragma unroll
    for (int i = 0; i < 8; i++) {
        int r = ro + (ty << 3) + i;
        float* dst0 = &g_Gx[r * 1024 + co + (tx << 2)];
        float4 v0 = {acc[i][0] + bias[0], acc[i][1] + bias[1],
                     acc[i][2] + bias[2], acc[i][3] + bias[3]};
        float4 v1 = {acc[i][4] + bias[4], acc[i][5] + bias[5],
                     acc[i][6] + bias[6], acc[i][7] + bias[7]};
        *(float4*)dst0 = v0;
        *(float4*)(dst0 + 64) = v1;
    }
}

// ---------------- kB: persistent LSTM recurrence ----------------
// 128 CTAs = 8 batch-groups x 16 hid-groups. Warp = k-slice (kq = tid>>5):
// h reads are pure smem broadcasts (N=1). Weights pre-packed (w0,w1) f32x2
// pairs in registers; h staged DUPLICATED so LDS.128 yields (h,h) splat pairs.
// Partials in s_p[kq][b][lc] with 68-float pad: conflict-free 8-B-stride store.
__global__ void __launch_bounds__(256) kB(const float* __restrict__ W)   // W_lstm
{
    __shared__ __align__(16) float s_h2[8 * 512];   // duplicated h: [b][2k]=[2k+1]=h[k]
    __shared__ __align__(16) float s_p[8 * 544];    // partials [kq][b*68 + lc]

    const int tid = threadIdx.x;
    const int bg = blockIdx.x >> 4;      // 0..7
    const int hg = blockIdx.x & 15;      // 0..15
    const int B0 = bg << 3;

    const int kq = tid >> 5;             // warp id = k slice (uniform per warp)
    const int cg = tid & 31;             // col pair
    const int lc0 = cg << 1;
    const int gc0 = ((lc0 >> 4) << 8) + (hg << 4) + (lc0 & 15);  // global gate col

    // packed weight pairs: wp[kk] = (W[k][gc0], W[k][gc0+1]) as f32x2
    ull wp[32];
#pragma unroll
    for (int kk = 0; kk < 32; kk++)
        wp[kk] = *(const ull*)(W + (256 + (kq << 5) + kk) * 1024 + gc0);

    const int rb = tid >> 4, rh = tid & 15;   // pointwise identity (tid<128)
    const int ghid = (hg << 4) + rh;
    float c_state = 0.0f;

    for (int t = 0; t < 64; t++) {
        // stage duplicated h: 8 batches x 512 floats = 1024 float4 / 256 thr
#pragma unroll
        for (int v = 0; v < 4; v++) {
            int li = tid + (v << 8);          // 0..1023
            int b = li >> 7, k2 = li & 127;   // k2 indexes float2 of source h
            float2 hv = ((const float2*)g_H)[((B0 + b) << 7) + k2];
            float4 st = {hv.x, hv.x, hv.y, hv.y};
            ((float4*)s_h2)[(b << 7) + k2] = st;
        }
        __syncthreads();

        ull acc2[8];
#pragma unroll
        for (int b = 0; b < 8; b++) acc2[b] = 0ull;
#pragma unroll
        for (int b = 0; b < 8; b++) {
            const ulonglong2* hp = (const ulonglong2*)(s_h2 + (b << 9) + (kq << 6));
#pragma unroll
            for (int q = 0; q < 16; q++) {
                ulonglong2 h2 = hp[q];          // .x=(h2q,h2q) .y=(h2q+1,h2q+1)
                FMA2(acc2[b], h2.x, wp[2 * q]);
                FMA2(acc2[b], h2.y, wp[2 * q + 1]);
            }
        }
#pragma unroll
        for (int b = 0; b < 8; b++)
            *(ull*)(s_p + kq * 544 + b * 68 + lc0) = acc2[b];   // 8-B stride: no conflict
        __syncthreads();

        if (tid < 128) {
            float sg[4];
#pragma unroll
            for (int g = 0; g < 4; g++) {
                float s = 0.0f;
#pragma unroll
                for (int q = 0; q < 8; q++)
                    s += s_p[q * 544 + rb * 68 + (g << 4) + rh];
                sg[g] = s;
            }
            const float* gx = g_Gx + (((B0 + rb) << 6) + t) * 1024 + ghid;
            float vi = sg[0] + gx[0];
            float vj = sg[1] + gx[256];
            float vf = sg[2] + gx[512];
            float vo = sg[3] + gx[768];
            c_state = sigm(vf + 1.0f) * c_state + sigm(vi) * tanhf(vj);
            float h = sigm(vo) * tanhf(c_state);
            g_H[((B0 + rb) << 8) + ghid] = h;
            g_hs[(((B0 + rb) << 6) + t) * 256 + ghid] = h;
        }

        if (t < 63) {   // grid barrier between steps
            __threadfence();
            __syncthreads();
            if (tid == 0) {
                atomicAdd(&g_bar[t], 1u);
                volatile unsigned* p = &g_bar[t];
                while (*p < 128u) { }
                __threadfence();
            }
            __syncthreads();
        }
    }
}

// ---------------- kC: hs @ W_dense + b, fused online-softmax partials ----------------
// 128x128 tile, K=256, 8x8 micro via packed FFMA2 (fma.rn.f32x2):
// A stored duplicated in smem -> LDS.128 gives ready (a,a) splat pairs;
// B pairs are the 64-bit aliases of the vector load. 32 FFMA2/k/thread.
__global__ void __launch_bounds__(256) kC(const float* __restrict__ Wd,
                                          const float* __restrict__ bd,
                                          const int* __restrict__ tgt)
{
    __shared__ __align__(16) float sm[6336];   // As2[16][264] + Bs[16][132]
    float* As2 = sm;
    float* Bs  = sm + 4224;
    const int tid = threadIdx.x;
    const int tx = tid & 15, ty = tid >> 4;
    const int ro = blockIdx.y << 7;
    const int co = blockIdx.x << 7;

    const int lrow = tid >> 1;
    const int lkb  = (tid & 1) << 3;
    const int bk   = tid >> 4;
    const int bcb  = (tid & 15) << 3;
    const bool tail = (co + 128 > VOCAB);

    ull acc2[8][4];
#pragma unroll
    for (int i = 0; i < 8; i++)
#pragma unroll
        for (int j = 0; j < 4; j++) acc2[i][j] = 0ull;

    float4 na0, na1, nb0, nb1;
    {
        const float* sa = g_hs + (ro + lrow) * 256 + lkb;
        na0 = *(const float4*)sa; na1 = *(const float4*)(sa + 4);
        const float* sb = Wd + bk * VOCAB + co + bcb;
        if (!tail) {
            nb0 = *(const float4*)sb; nb1 = *(const float4*)(sb + 4);
        } else {
            float e[8];
#pragma unroll
            for (int q = 0; q < 8; q++) e[q] = (co + bcb + q < VOCAB) ? sb[q] : 0.0f;
            nb0 = {e[0], e[1], e[2], e[3]}; nb1 = {e[4], e[5], e[6], e[7]};
        }
    }

    for (int kt = 0; kt < 16; kt++) {
        __syncthreads();
        {   // A duplicated: As2[k][2r] = As2[k][2r+1] = A[r][k]
            float av[8] = {na0.x, na0.y, na0.z, na0.w, na1.x, na1.y, na1.z, na1.w};
#pragma unroll
            for (int e = 0; e < 8; e++) {
                float2 d2 = {av[e], av[e]};
                *(float2*)(As2 + (lkb + e) * 264 + (lrow << 1)) = d2;
            }
            float* db = Bs + bk * 132 + bcb;
            *(float4*)db = nb0; *(float4*)(db + 4) = nb1;
        }
        __syncthreads();
        if (kt < 15) {
            int k0 = (kt + 1) << 4;
            const float* sa = g_hs + (ro + lrow) * 256 + k0 + lkb;
            na0 = *(const float4*)sa; na1 = *(const float4*)(sa + 4);
            const float* sb = Wd + (k0 + bk) * VOCAB + co + bcb;
            if (!tail) {
                nb0 = *(const float4*)sb; nb1 = *(const float4*)(sb + 4);
            } else {
                float e[8];
#pragma unroll
                for (int q = 0; q < 8; q++) e[q] = (co + bcb + q < VOCAB) ? sb[q] : 0.0f;
                nb0 = {e[0], e[1], e[2], e[3]}; nb1 = {e[4], e[5], e[6], e[7]};
            }
        }
#pragma unroll
        for (int k = 0; k < 16; k++) {
            const float* ab = As2 + k * 264 + (ty << 4);
            ulonglong2 q0 = *(const ulonglong2*)(ab);        // splat rows 0,1
            ulonglong2 q1 = *(const ulonglong2*)(ab + 4);    // rows 2,3
            ulonglong2 q2 = *(const ulonglong2*)(ab + 8);    // rows 4,5
            ulonglong2 q3 = *(const ulonglong2*)(ab + 12);   // rows 6,7
            ulonglong2 r0 = *(const ulonglong2*)(Bs + k * 132 + (tx << 2));       // (b0b1,b2b3)
            ulonglong2 r1 = *(const ulonglong2*)(Bs + k * 132 + 64 + (tx << 2));  // (b4b5,b6b7)
            ull aa[8] = {q0.x, q0.y, q1.x, q1.y, q2.x, q2.y, q3.x, q3.y};
            ull bb[4] = {r0.x, r0.y, r1.x, r1.y};
#pragma unroll
            for (int i = 0; i < 8; i++) {
                FMA2(acc2[i][0], aa[i], bb[0]);
                FMA2(acc2[i][1], aa[i], bb[1]);
                FMA2(acc2[i][2], aa[i], bb[2]);
                FMA2(acc2[i][3], aa[i], bb[3]);
            }
        }
    }

    // epilogue: unpack, bias, target-logit capture, row max / sumexp
    int   gcol[8];
    float bias[8];
    bool  valid[8];
#pragma unroll
    for (int j = 0; j < 8; j++) {
        int gc = co + ((j < 4) ? ((tx << 2) + j) : (64 + (tx << 2) + j - 4));
        gcol[j] = gc;
        valid[j] = (gc < VOCAB);
        bias[j] = valid[j] ? bd[gc] : 0.0f;
    }
    float m[8], s[8];
#pragma unroll
    for (int i = 0; i < 8; i++) {
        float l[8];
#pragma unroll
        for (int jp = 0; jp < 4; jp++)
            UNPK2(l[2 * jp], l[2 * jp + 1], acc2[i][jp]);
        int gr = ro + (ty << 3) + i;
        int tg = tgt[gr];
        float mi = -1e30f;
#pragma unroll
        for (int j = 0; j < 8; j++) {
            float lv = valid[j] ? (l[j] + bias[j]) : -1e30f;
            l[j] = lv;
            if (valid[j] && gcol[j] == tg) g_lt[gr] = lv;
            mi = fmaxf(mi, lv);
        }
        float si = 0.0f;
#pragma unroll
        for (int j = 0; j < 8; j++) si += __expf(l[j] - mi);
        m[i] = mi; s[i] = si;
    }

    __syncthreads();   // reuse smem for reduction
    float* redm = sm;          // [128][16]
    float* reds = sm + 2048;   // [128][16]
#pragma unroll
    for (int i = 0; i < 8; i++) {
        redm[((ty << 3) + i) * 16 + tx] = m[i];
        reds[((ty << 3) + i) * 16 + tx] = s[i];
    }
    __syncthreads();
    if (tid < 128) {
        float M = -1e30f;
#pragma unroll
        for (int x = 0; x < 16; x++) M = fmaxf(M, redm[tid * 16 + x]);
        float S = 0.0f;
#pragma unroll
        for (int x = 0; x < 16; x++) S += reds[tid * 16 + x] * __expf(redm[tid * 16 + x] - M);
        g_pmax[blockIdx.x * 4096 + ro + tid] = M;
        g_psum[blockIdx.x * 4096 + ro + tid] = S;
    }
}

// ---------------- kD: combine partials -> perplexity ----------------
__global__ void kD(float* __restrict__ out)
{
    int r = blockIdx.x * 128 + threadIdx.x;   // = b*64 + t
    float M = g_pmax[r];
    float S = g_psum[r];
    for (int i = 1; i < 79; i++) {
        float mi = g_pmax[i * 4096 + r];
        float si = g_psum[i * 4096 + r];
        float nm = fmaxf(M, mi);
        S = S * __expf(M - nm) + si * __expf(mi - nm);
        M = nm;
    }
    out[r] = S * __expf(M - g_lt[r]);   // ppl = sumexp * exp(max - target_logit)
}

// ---------------- launch ----------------
extern "C" void kernel_launch(void* const* d_in, const int* in_sizes, int n_in,
                              void* d_out, int out_size)
{
    const int*   input_data = (const int*)d_in[0];
    const int*   targets    = (const int*)d_in[1];
    const float* E          = (const float*)d_in[2];
    const float* W_lstm     = (const float*)d_in[3];
    const float* b_lstm     = (const float*)d_in[4];
    const float* W_dense    = (const float*)d_in[5];
    const float* b_dense    = (const float*)d_in[6];
    float* out = (float*)d_out;
    (void)in_sizes; (void)n_in; (void)out_size;

    k_init<<<64, 256>>>();
    kA<<<dim3(8, 32), 256>>>(input_data, E, W_lstm, b_lstm);
    kB<<<128, 256>>>(W_lstm);
    kC<<<dim3(79, 32), 256>>>(W_dense, b_dense, targets);
    kD<<<32, 128>>>(out);
}

// round 7
// speedup vs baseline: 1.6177x; 1.0917x over previous
#include <cuda_runtime.h>
#include <math.h>

#define VOCAB 10000

// ---------------- scratch (static device globals; no allocation) ----------------
static __device__ float    g_Gx[4096 * 1024];   // input-proj gates [row=b*64+t][1024]
static __device__ float    g_H[64 * 256];       // current hidden state [b][h]
static __device__ float    g_hs[4096 * 256];    // all hidden states [row][h]
static __device__ unsigned g_bar[64];           // per-step grid barrier counters
static __device__ float    g_pmax[79 * 4096];   // softmax partial max   [tile][row]
static __device__ float    g_psum[79 * 4096];   // softmax partial sumexp[tile][row]
static __device__ float    g_lt[4096];          // target logit per row

__device__ __forceinline__ float sigm(float x) { return 1.0f / (1.0f + __expf(-x)); }

// ---------------- init ----------------
__global__ void k_init()
{
    int t = blockIdx.x * blockDim.x + threadIdx.x;
    if (t < 64 * 256) g_H[t] = 0.0f;
    if (t < 64) g_bar[t] = 0u;
}

// ---------------- kA: embedding gather + X @ Wx + b -> g_Gx ----------------
// 128x128 tile, K=256, 8x8 micro, conflict-free frags, reg double-buffer.
__global__ void __launch_bounds__(256) kA(const int* __restrict__ idx,
                                          const float* __restrict__ E,
                                          const float* __restrict__ W,   // [512][1024]
                                          const float* __restrict__ bl)
{
    __shared__ __align__(16) float sm[4224];
    float* As = sm;            // [16][132] transposed: As[k][row]
    float* Bs = sm + 2112;     // [16][132]
    const int tid = threadIdx.x;
    const int tx = tid & 15, ty = tid >> 4;
    const int ro = blockIdx.y << 7;
    const int co = blockIdx.x << 7;

    const int lrow = tid >> 1;
    const int lkb  = (tid & 1) << 3;
    const int erow = idx[ro + lrow];
    const int bk   = tid >> 4;
    const int bcb  = (tid & 15) << 3;

    float acc[8][8] = {};
    float4 na0, na1, nb0, nb1;

    {
        const float* sa = E + erow * 256 + lkb;
        na0 = *(const float4*)sa; na1 = *(const float4*)(sa + 4);
        const float* sb = W + bk * 1024 + co + bcb;
        nb0 = *(const float4*)sb; nb1 = *(const float4*)(sb + 4);
    }

    for (int kt = 0; kt < 16; kt++) {
        __syncthreads();
        {
            float* d = As + lrow;
            d[(lkb + 0) * 132] = na0.x; d[(lkb + 1) * 132] = na0.y;
            d[(lkb + 2) * 132] = na0.z; d[(lkb + 3) * 132] = na0.w;
            d[(lkb + 4) * 132] = na1.x; d[(lkb + 5) * 132] = na1.y;
            d[(lkb + 6) * 132] = na1.z; d[(lkb + 7) * 132] = na1.w;
            float* db = Bs + bk * 132 + bcb;
            *(float4*)db = nb0; *(float4*)(db + 4) = nb1;
        }
        __syncthreads();
        if (kt < 15) {
            int k0 = (kt + 1) << 4;
            const float* sa = E + erow * 256 + k0 + lkb;
            na0 = *(const float4*)sa; na1 = *(const float4*)(sa + 4);
            const float* sb = W + (k0 + bk) * 1024 + co + bcb;
            nb0 = *(const float4*)sb; nb1 = *(const float4*)(sb + 4);
        }
#pragma unroll
        for (int k = 0; k < 16; k++) {
            float4 a0 = *(const float4*)(As + k * 132 + (ty << 3));
            float4 a1 = *(const float4*)(As + k * 132 + (ty << 3) + 4);
            float4 b0 = *(const float4*)(Bs + k * 132 + (tx << 2));
            float4 b1 = *(const float4*)(Bs + k * 132 + 64 + (tx << 2));
            float a[8] = {a0.x, a0.y, a0.z, a0.w, a1.x, a1.y, a1.z, a1.w};
            float b[8] = {b0.x, b0.y, b0.z, b0.w, b1.x, b1.y, b1.z, b1.w};
#pragma unroll
            for (int i = 0; i < 8; i++)
#pragma unroll
                for (int j = 0; j < 8; j++)
                    acc[i][j] = fmaf(a[i], b[j], acc[i][j]);
        }
    }

    float bias[8];
#pragma unroll
    for (int j = 0; j < 8; j++) {
        int gc = co + ((j < 4) ? ((tx << 2) + j) : (64 + (tx << 2) + j - 4));
        bias[j] = bl[gc];
    }
#pragma unroll
    for (int i = 0; i < 8; i++) {
        int r = ro + (ty << 3) + i;
        float* dst0 = &g_Gx[r * 1024 + co + (tx << 2)];
        float4 v0 = {acc[i][0] + bias[0], acc[i][1] + bias[1],
                     acc[i][2] + bias[2], acc[i][3] + bias[3]};
        float4 v1 = {acc[i][4] + bias[4], acc[i][5] + bias[5],
                     acc[i][6] + bias[6], acc[i][7] + bias[7]};
        *(float4*)dst0 = v0;
        *(float4*)(dst0 + 64) = v1;
    }
}

// ---------------- kB: persistent LSTM recurrence (scalar FFMA) ----------------
// 128 CTAs = 8 batch-groups x 16 hid-groups. Warp = k-slice (kq = tid>>5):
// all s_h reads are bank-broadcasts (N=1). Scalar weight regs w0/w1.
// Partials: s_p[kq][b*68 + lc] stored as float2 -> 8-B lane stride, no conflicts.
__global__ void __launch_bounds__(256) kB(const float* __restrict__ W)   // W_lstm
{
    __shared__ __align__(16) float s_h[8 * 256];    // staged h [b][k]
    __shared__ __align__(16) float s_p[8 * 544];    // partials [kq][b*68 + lc]

    const int tid = threadIdx.x;
    const int bg = blockIdx.x >> 4;      // 0..7
    const int hg = blockIdx.x & 15;      // 0..15
    const int B0 = bg << 3;

    const int kq = tid >> 5;             // warp id = k slice (uniform per warp)
    const int cg = tid & 31;             // col pair
    const int lc0 = cg << 1;
    const int gc0 = ((lc0 >> 4) << 8) + (hg << 4) + (lc0 & 15);  // global gate col

    float w0[32], w1[32];
#pragma unroll
    for (int kk = 0; kk < 32; kk++) {
        const float* wr = W + (256 + (kq << 5) + kk) * 1024 + gc0;
        w0[kk] = wr[0];
        w1[kk] = wr[1];
    }

    const int rb = tid >> 4, rh = tid & 15;   // pointwise identity (tid<128)
    const int ghid = (hg << 4) + rh;
    float c_state = 0.0f;

    for (int t = 0; t < 64; t++) {
        // stage h[8 batches][256] into smem: 512 float4 over 256 threads
#pragma unroll
        for (int v = 0; v < 2; v++) {
            int li = tid + (v << 8);
            int b = li >> 6, k4 = li & 63;
            ((float4*)s_h)[(b << 6) + k4] = ((const float4*)g_H)[((B0 + b) << 6) + k4];
        }
        __syncthreads();

#pragma unroll
        for (int b = 0; b < 8; b++) {
            const float4* hp = (const float4*)(s_h + (b << 8) + (kq << 5));
            float a0 = 0.0f, a1 = 0.0f;
#pragma unroll
            for (int q = 0; q < 8; q++) {
                float4 h4 = hp[q];      // broadcast within warp
                a0 = fmaf(h4.x, w0[4 * q + 0], a0); a1 = fmaf(h4.x, w1[4 * q + 0], a1);
                a0 = fmaf(h4.y, w0[4 * q + 1], a0); a1 = fmaf(h4.y, w1[4 * q + 1], a1);
                a0 = fmaf(h4.z, w0[4 * q + 2], a0); a1 = fmaf(h4.z, w1[4 * q + 2], a1);
                a0 = fmaf(h4.w, w0[4 * q + 3], a0); a1 = fmaf(h4.w, w1[4 * q + 3], a1);
            }
            float2 pv = {a0, a1};
            *(float2*)(s_p + kq * 544 + b * 68 + lc0) = pv;   // 8-B stride: conflict-free
        }
        __syncthreads();

        if (tid < 128) {
            float sg[4];
#pragma unroll
            for (int g = 0; g < 4; g++) {
                float s = 0.0f;
#pragma unroll
                for (int q = 0; q < 8; q++)
                    s += s_p[q * 544 + rb * 68 + (g << 4) + rh];
                sg[g] = s;
            }
            const float* gx = g_Gx + (((B0 + rb) << 6) + t) * 1024 + ghid;
            float vi = sg[0] + gx[0];
            float vj = sg[1] + gx[256];
            float vf = sg[2] + gx[512];
            float vo = sg[3] + gx[768];
            c_state = sigm(vf + 1.0f) * c_state + sigm(vi) * tanhf(vj);
            float h = sigm(vo) * tanhf(c_state);
            g_H[((B0 + rb) << 8) + ghid] = h;
            g_hs[(((B0 + rb) << 6) + t) * 256 + ghid] = h;
        }

        if (t < 63) {   // grid barrier between steps
            __threadfence();
            __syncthreads();
            if (tid == 0) {
                atomicAdd(&g_bar[t], 1u);
                volatile unsigned* p = &g_bar[t];
                while (*p < 128u) { }
                __threadfence();
            }
            __syncthreads();
        }
    }
}

// ---------------- kC: hs @ W_dense + b, fused online-softmax partials ----------------
// 128x128 tile, K=256, 8x8 scalar micro, PING-PONG smem double buffer:
// one __syncthreads per k-stage; store targets the idle buffer.
__global__ void __launch_bounds__(256) kC(const float* __restrict__ Wd,
                                          const float* __restrict__ bd,
                                          const int* __restrict__ tgt)
{
    __shared__ __align__(16) float sm[8448];      // 2 x (As[16][132] + Bs[16][132])
    const int tid = threadIdx.x;
    const int tx = tid & 15, ty = tid >> 4;
    const int ro = blockIdx.y << 7;
    const int co = blockIdx.x << 7;

    const int lrow = tid >> 1;
    const int lkb  = (tid & 1) << 3;
    const int bk   = tid >> 4;
    const int bcb  = (tid & 15) << 3;
    const bool tail = (co + 128 > VOCAB);

    float acc[8][8] = {};
    float4 na0, na1, nb0, nb1;

    // prefetch stage 0 to regs
    {
        const float* sa = g_hs + (ro + lrow) * 256 + lkb;
        na0 = *(const float4*)sa; na1 = *(const float4*)(sa + 4);
        const float* sb = Wd + bk * VOCAB + co + bcb;
        if (!tail) {
            nb0 = *(const float4*)sb; nb1 = *(const float4*)(sb + 4);
        } else {
            float e[8];
#pragma unroll
            for (int q = 0; q < 8; q++) e[q] = (co + bcb + q < VOCAB) ? sb[q] : 0.0f;
            nb0 = {e[0], e[1], e[2], e[3]}; nb1 = {e[4], e[5], e[6], e[7]};
        }
    }
    // store stage 0 into buffer 0
    {
        float* As = sm;
        float* d = As + lrow;
        d[(lkb + 0) * 132] = na0.x; d[(lkb + 1) * 132] = na0.y;
        d[(lkb + 2) * 132] = na0.z; d[(lkb + 3) * 132] = na0.w;
        d[(lkb + 4) * 132] = na1.x; d[(lkb + 5) * 132] = na1.y;
        d[(lkb + 6) * 132] = na1.z; d[(lkb + 7) * 132] = na1.w;
        float* db = sm + 2112 + bk * 132 + bcb;
        *(float4*)db = nb0; *(float4*)(db + 4) = nb1;
    }
    __syncthreads();

    for (int kt = 0; kt < 16; kt++) {
        const int cur = kt & 1;
        float* As = sm + cur * 4224;
        float* Bs = sm + cur * 4224 + 2112;

        // prefetch next stage to regs (overlaps with compute below)
        if (kt < 15) {
            int k0 = (kt + 1) << 4;
            const float* sa = g_hs + (ro + lrow) * 256 + k0 + lkb;
            na0 = *(const float4*)sa; na1 = *(const float4*)(sa + 4);
            const float* sb = Wd + (k0 + bk) * VOCAB + co + bcb;
            if (!tail) {
                nb0 = *(const float4*)sb; nb1 = *(const float4*)(sb + 4);
            } else {
                float e[8];
#pragma unroll
                for (int q = 0; q < 8; q++) e[q] = (co + bcb + q < VOCAB) ? sb[q] : 0.0f;
                nb0 = {e[0], e[1], e[2], e[3]}; nb1 = {e[4], e[5], e[6], e[7]};
            }
        }

#pragma unroll
        for (int k = 0; k < 16; k++) {
            float4 a0 = *(const float4*)(As + k * 132 + (ty << 3));
            float4 a1 = *(const float4*)(As + k * 132 + (ty << 3) + 4);
            float4 b0 = *(const float4*)(Bs + k * 132 + (tx << 2));
            float4 b1 = *(const float4*)(Bs + k * 132 + 64 + (tx << 2));
            float a[8] = {a0.x, a0.y, a0.z, a0.w, a1.x, a1.y, a1.z, a1.w};
            float b[8] = {b0.x, b0.y, b0.z, b0.w, b1.x, b1.y, b1.z, b1.w};
#pragma unroll
            for (int i = 0; i < 8; i++)
#pragma unroll
                for (int j = 0; j < 8; j++)
                    acc[i][j] = fmaf(a[i], b[j], acc[i][j]);
        }

        // store next stage into the OTHER buffer, single barrier per stage
        if (kt < 15) {
            float* Asn = sm + (cur ^ 1) * 4224;
            float* d = Asn + lrow;
            d[(lkb + 0) * 132] = na0.x; d[(lkb + 1) * 132] = na0.y;
            d[(lkb + 2) * 132] = na0.z; d[(lkb + 3) * 132] = na0.w;
            d[(lkb + 4) * 132] = na1.x; d[(lkb + 5) * 132] = na1.y;
            d[(lkb + 6) * 132] = na1.z; d[(lkb + 7) * 132] = na1.w;
            float* db = sm + (cur ^ 1) * 4224 + 2112 + bk * 132 + bcb;
            *(float4*)db = nb0; *(float4*)(db + 4) = nb1;
            __syncthreads();
        }
    }

    // epilogue: bias, target-logit capture, per-thread row max/sumexp
    int   gcol[8];
    float bias[8];
    bool  valid[8];
#pragma unroll
    for (int j = 0; j < 8; j++) {
        int gc = co + ((j < 4) ? ((tx << 2) + j) : (64 + (tx << 2) + j - 4));
        gcol[j] = gc;
        valid[j] = (gc < VOCAB);
        bias[j] = valid[j] ? bd[gc] : 0.0f;
    }
    float m[8], s[8];
#pragma unroll
    for (int i = 0; i < 8; i++) {
        int gr = ro + (ty << 3) + i;
        int tg = tgt[gr];
        float mi = -1e30f;
#pragma unroll
        for (int j = 0; j < 8; j++) {
            float l = valid[j] ? (acc[i][j] + bias[j]) : -1e30f;
            acc[i][j] = l;
            if (valid[j] && gcol[j] == tg) g_lt[gr] = l;
            mi = fmaxf(mi, l);
        }
        float si = 0.0f;
#pragma unroll
        for (int j = 0; j < 8; j++) si += __expf(acc[i][j] - mi);
        m[i] = mi; s[i] = si;
    }

    __syncthreads();   // reuse smem for reduction
    float* redm = sm;          // [128][16]
    float* reds = sm + 2048;   // [128][16]
#pragma unroll
    for (int i = 0; i < 8; i++) {
        redm[((ty << 3) + i) * 16 + tx] = m[i];
        reds[((ty << 3) + i) * 16 + tx] = s[i];
    }
    __syncthreads();
    if (tid < 128) {
        float M = -1e30f;
#pragma unroll
        for (int x = 0; x < 16; x++) M = fmaxf(M, redm[tid * 16 + x]);
        float S = 0.0f;
#pragma unroll
        for (int x = 0; x < 16; x++) S += reds[tid * 16 + x] * __expf(redm[tid * 16 + x] - M);
        g_pmax[blockIdx.x * 4096 + ro + tid] = M;
        g_psum[blockIdx.x * 4096 + ro + tid] = S;
    }
}

// ---------------- kD: combine partials -> perplexity ----------------
__global__ void kD(float* __restrict__ out)
{
    int r = blockIdx.x * 128 + threadIdx.x;   // = b*64 + t
    float M = g_pmax[r];
    float S = g_psum[r];
    for (int i = 1; i < 79; i++) {
        float mi = g_pmax[i * 4096 + r];
        float si = g_psum[i * 4096 + r];
        float nm = fmaxf(M, mi);
        S = S * __expf(M - nm) + si * __expf(mi - nm);
        M = nm;
    }
    out[r] = S * __expf(M - g_lt[r]);   // ppl = sumexp * exp(max - target_logit)
}

// ---------------- launch ----------------
extern "C" void kernel_launch(void* const* d_in, const int* in_sizes, int n_in,
                              void* d_out, int out_size)
{
    const int*   input_data = (const int*)d_in[0];
    const int*   targets    = (const int*)d_in[1];
    const float* E          = (const float*)d_in[2];
    const float* W_lstm     = (const float*)d_in[3];
    const float* b_lstm     = (const float*)d_in[4];
    const float* W_dense    = (const float*)d_in[5];
    const float* b_dense    = (const float*)d_in[6];
    float* out = (float*)d_out;
    (void)in_sizes; (void)n_in; (void)out_size;

    k_init<<<64, 256>>>();
    kA<<<dim3(8, 32), 256>>>(input_data, E, W_lstm, b_lstm);
    kB<<<128, 256>>>(W_lstm);
    kC<<<dim3(79, 32), 256>>>(W_dense, b_dense, targets);
    kD<<<32, 128>>>(out);
}

// round 8
// speedup vs baseline: 1.7110x; 1.0577x over previous
#include <cuda_runtime.h>
#include <math.h>

#define VOCAB 10000

// ---------------- scratch (static device globals; no allocation) ----------------
static __device__ float    g_Gx[4096 * 1024];   // input-proj gates [row=b*64+t][1024]
static __device__ float    g_H[64 * 256];       // current hidden state [b][h]
static __device__ float    g_hsT[256 * 4096];   // hidden states TRANSPOSED [k][row]
static __device__ unsigned g_bar[64];           // per-step grid barrier counters
static __device__ float    g_pmax[79 * 4096];   // softmax partial max   [tile][row]
static __device__ float    g_psum[79 * 4096];   // softmax partial sumexp[tile][row]
static __device__ float    g_lt[4096];          // target logit per row

__device__ __forceinline__ float sigm(float x) { return 1.0f / (1.0f + __expf(-x)); }

__device__ __forceinline__ void cp16(unsigned dst, const void* src, int bytes)
{
    asm volatile("cp.async.cg.shared.global [%0], [%1], 16, %2;"
                 :: "r"(dst), "l"(src), "r"(bytes));
}

// ---------------- init ----------------
__global__ void k_init()
{
    int t = blockIdx.x * blockDim.x + threadIdx.x;
    if (t < 64 * 256) g_H[t] = 0.0f;
    if (t < 64) g_bar[t] = 0u;
}

// ---------------- kA: embedding gather + X @ Wx + b -> g_Gx ----------------
// 128x128 tile, K=256, 8x8 micro, conflict-free frags, reg double-buffer.
__global__ void __launch_bounds__(256) kA(const int* __restrict__ idx,
                                          const float* __restrict__ E,
                                          const float* __restrict__ W,   // [512][1024]
                                          const float* __restrict__ bl)
{
    __shared__ __align__(16) float sm[4224];
    float* As = sm;            // [16][132] transposed: As[k][row]
    float* Bs = sm + 2112;     // [16][132]
    const int tid = threadIdx.x;
    const int tx = tid & 15, ty = tid >> 4;
    const int ro = blockIdx.y << 7;
    const int co = blockIdx.x << 7;

    const int lrow = tid >> 1;
    const int lkb  = (tid & 1) << 3;
    const int erow = idx[ro + lrow];
    const int bk   = tid >> 4;
    const int bcb  = (tid & 15) << 3;

    float acc[8][8] = {};
    float4 na0, na1, nb0, nb1;

    {
        const float* sa = E + erow * 256 + lkb;
        na0 = *(const float4*)sa; na1 = *(const float4*)(sa + 4);
        const float* sb = W + bk * 1024 + co + bcb;
        nb0 = *(const float4*)sb; nb1 = *(const float4*)(sb + 4);
    }

    for (int kt = 0; kt < 16; kt++) {
        __syncthreads();
        {
            float* d = As + lrow;
            d[(lkb + 0) * 132] = na0.x; d[(lkb + 1) * 132] = na0.y;
            d[(lkb + 2) * 132] = na0.z; d[(lkb + 3) * 132] = na0.w;
            d[(lkb + 4) * 132] = na1.x; d[(lkb + 5) * 132] = na1.y;
            d[(lkb + 6) * 132] = na1.z; d[(lkb + 7) * 132] = na1.w;
            float* db = Bs + bk * 132 + bcb;
            *(float4*)db = nb0; *(float4*)(db + 4) = nb1;
        }
        __syncthreads();
        if (kt < 15) {
            int k0 = (kt + 1) << 4;
            const float* sa = E + erow * 256 + k0 + lkb;
            na0 = *(const float4*)sa; na1 = *(const float4*)(sa + 4);
            const float* sb = W + (k0 + bk) * 1024 + co + bcb;
            nb0 = *(const float4*)sb; nb1 = *(const float4*)(sb + 4);
        }
#pragma unroll
        for (int k = 0; k < 16; k++) {
            float4 a0 = *(const float4*)(As + k * 132 + (ty << 3));
            float4 a1 = *(const float4*)(As + k * 132 + (ty << 3) + 4);
            float4 b0 = *(const float4*)(Bs + k * 132 + (tx << 2));
            float4 b1 = *(const float4*)(Bs + k * 132 + 64 + (tx << 2));
            float a[8] = {a0.x, a0.y, a0.z, a0.w, a1.x, a1.y, a1.z, a1.w};
            float b[8] = {b0.x, b0.y, b0.z, b0.w, b1.x, b1.y, b1.z, b1.w};
#pragma unroll
            for (int i = 0; i < 8; i++)
#pragma unroll
                for (int j = 0; j < 8; j++)
                    acc[i][j] = fmaf(a[i], b[j], acc[i][j]);
        }
    }

    float bias[8];
#pragma unroll
    for (int j = 0; j < 8; j++) {
        int gc = co + ((j < 4) ? ((tx << 2) + j) : (64 + (tx << 2) + j - 4));
        bias[j] = bl[gc];
    }
#pragma unroll
    for (int i = 0; i < 8; i++) {
        int r = ro + (ty << 3) + i;
        float* dst0 = &g_Gx[r * 1024 + co + (tx << 2)];
        float4 v0 = {acc[i][0] + bias[0], acc[i][1] + bias[1],
                     acc[i][2] + bias[2], acc[i][3] + bias[3]};
        float4 v1 = {acc[i][4] + bias[4], acc[i][5] + bias[5],
                     acc[i][6] + bias[6], acc[i][7] + bias[7]};
        *(float4*)dst0 = v0;
        *(float4*)(dst0 + 64) = v1;
    }
}

// ---------------- kB: persistent LSTM recurrence (scalar FFMA) ----------------
// 128 CTAs = 8 batch-groups x 16 hid-groups. Warp = k-slice (kq = tid>>5):
// all s_h reads are bank-broadcasts (N=1). Scalar weight regs w0/w1.
// Partials: s_p[kq][b*68 + lc] stored as float2 -> 8-B lane stride, no conflicts.
// h is written TRANSPOSED to g_hsT[k][row] for kC's coalesced A loads.
__global__ void __launch_bounds__(256) kB(const float* __restrict__ W)   // W_lstm
{
    __shared__ __align__(16) float s_h[8 * 256];    // staged h [b][k]
    __shared__ __align__(16) float s_p[8 * 544];    // partials [kq][b*68 + lc]

    const int tid = threadIdx.x;
    const int bg = blockIdx.x >> 4;      // 0..7
    const int hg = blockIdx.x & 15;      // 0..15
    const int B0 = bg << 3;

    const int kq = tid >> 5;             // warp id = k slice (uniform per warp)
    const int cg = tid & 31;             // col pair
    const int lc0 = cg << 1;
    const int gc0 = ((lc0 >> 4) << 8) + (hg << 4) + (lc0 & 15);  // global gate col

    float w0[32], w1[32];
#pragma unroll
    for (int kk = 0; kk < 32; kk++) {
        const float* wr = W + (256 + (kq << 5) + kk) * 1024 + gc0;
        w0[kk] = wr[0];
        w1[kk] = wr[1];
    }

    const int rb = tid >> 4, rh = tid & 15;   // pointwise identity (tid<128)
    const int ghid = (hg << 4) + rh;
    float c_state = 0.0f;

    for (int t = 0; t < 64; t++) {
        // stage h[8 batches][256] into smem: 512 float4 over 256 threads
#pragma unroll
        for (int v = 0; v < 2; v++) {
            int li = tid + (v << 8);
            int b = li >> 6, k4 = li & 63;
            ((float4*)s_h)[(b << 6) + k4] = ((const float4*)g_H)[((B0 + b) << 6) + k4];
        }
        __syncthreads();

#pragma unroll
        for (int b = 0; b < 8; b++) {
            const float4* hp = (const float4*)(s_h + (b << 8) + (kq << 5));
            float a0 = 0.0f, a1 = 0.0f;
#pragma unroll
            for (int q = 0; q < 8; q++) {
                float4 h4 = hp[q];      // broadcast within warp
                a0 = fmaf(h4.x, w0[4 * q + 0], a0); a1 = fmaf(h4.x, w1[4 * q + 0], a1);
                a0 = fmaf(h4.y, w0[4 * q + 1], a0); a1 = fmaf(h4.y, w1[4 * q + 1], a1);
                a0 = fmaf(h4.z, w0[4 * q + 2], a0); a1 = fmaf(h4.z, w1[4 * q + 2], a1);
                a0 = fmaf(h4.w, w0[4 * q + 3], a0); a1 = fmaf(h4.w, w1[4 * q + 3], a1);
            }
            float2 pv = {a0, a1};
            *(float2*)(s_p + kq * 544 + b * 68 + lc0) = pv;   // 8-B stride: conflict-free
        }
        __syncthreads();

        if (tid < 128) {
            float sg[4];
#pragma unroll
            for (int g = 0; g < 4; g++) {
                float s = 0.0f;
#pragma unroll
                for (int q = 0; q < 8; q++)
                    s += s_p[q * 544 + rb * 68 + (g << 4) + rh];
                sg[g] = s;
            }
            const float* gx = g_Gx + (((B0 + rb) << 6) + t) * 1024 + ghid;
            float vi = sg[0] + gx[0];
            float vj = sg[1] + gx[256];
            float vf = sg[2] + gx[512];
            float vo = sg[3] + gx[768];
            c_state = sigm(vf + 1.0f) * c_state + sigm(vi) * tanhf(vj);
            float h = sigm(vo) * tanhf(c_state);
            g_H[((B0 + rb) << 8) + ghid] = h;
            g_hsT[ghid * 4096 + ((B0 + rb) << 6) + t] = h;   // transposed for kC
        }

        if (t < 63) {   // grid barrier between steps
            __threadfence();
            __syncthreads();
            if (tid == 0) {
                atomicAdd(&g_bar[t], 1u);
                volatile unsigned* p = &g_bar[t];
                while (*p < 128u) { }
                __threadfence();
            }
            __syncthreads();
        }
    }
}

// ---------------- kC: hsT^T @ W_dense + b, fused online-softmax partials ----------
// 128x128 tile, K=256, 8x8 scalar micro. 3-stage cp.async pipeline (K-stage = 16),
// no reg round-trip, no transpose STS (A already k-major in g_hsT). Smem stride 128
// (conflict-free: cp.async rows are 512-B contiguous per warp; frag reads unchanged).
__global__ void __launch_bounds__(256) kC(const float* __restrict__ Wd,
                                          const float* __restrict__ bd,
                                          const int* __restrict__ tgt)
{
    __shared__ __align__(16) float sm[12288];     // 3 x (As[16][128] + Bs[16][128])
    const int tid = threadIdx.x;
    const int tx = tid & 15, ty = tid >> 4;
    const int ro = blockIdx.y << 7;
    const int co = blockIdx.x << 7;

    const int lk  = tid >> 5;            // loader k 0..7 (uniform per warp)
    const int lc4 = (tid & 31) << 2;     // loader col base 0..124

    const unsigned sbase = (unsigned)__cvta_generic_to_shared(sm);

    // issue one 16-k stage's cp.async loads into buffer buf
    auto issue = [&](int stage, int buf) {
        const unsigned Asb = sbase + buf * 16384u;        // bytes
        const unsigned Bsb = Asb + 8192u;
        const int k0 = stage << 4;
#pragma unroll
        for (int h = 0; h < 2; h++) {
            const int k = lk + (h << 3);
            cp16(Asb + (k << 9) + (lc4 << 2),
                 g_hsT + ((k0 + k) << 12) + ro + lc4, 16);
            const int gb = co + lc4;
            const int rem = VOCAB - gb;
            const int bytes = (rem >= 4) ? 16 : ((rem > 0) ? (rem << 2) : 0);
            const float* srcb = Wd + (k0 + k) * VOCAB + ((rem > 0) ? gb : 0);
            cp16(Bsb + (k << 9) + (lc4 << 2), srcb, bytes);
        }
    };

    float acc[8][8] = {};

    issue(0, 0);
    asm volatile("cp.async.commit_group;");
    issue(1, 1);
    asm volatile("cp.async.commit_group;");

    int bufc = 0;
    for (int i = 0; i < 16; i++) {
        if (i < 15) asm volatile("cp.async.wait_group 1;");
        else        asm volatile("cp.async.wait_group 0;");
        __syncthreads();

        const float* As = sm + bufc * 4096;
        const float* Bs = As + 2048;
#pragma unroll
        for (int k = 0; k < 16; k++) {
            float4 a0 = *(const float4*)(As + (k << 7) + (ty << 3));
            float4 a1 = *(const float4*)(As + (k << 7) + (ty << 3) + 4);
            float4 b0 = *(const float4*)(Bs + (k << 7) + (tx << 2));
            float4 b1 = *(const float4*)(Bs + (k << 7) + 64 + (tx << 2));
            float a[8] = {a0.x, a0.y, a0.z, a0.w, a1.x, a1.y, a1.z, a1.w};
            float b[8] = {b0.x, b0.y, b0.z, b0.w, b1.x, b1.y, b1.z, b1.w};
#pragma unroll
            for (int ii = 0; ii < 8; ii++)
#pragma unroll
                for (int jj = 0; jj < 8; jj++)
                    acc[ii][jj] = fmaf(a[ii], b[jj], acc[ii][jj]);
        }

        if (i + 2 < 16) {
            int nb = bufc + 2; if (nb >= 3) nb -= 3;
            issue(i + 2, nb);
        }
        asm volatile("cp.async.commit_group;");
        if (++bufc == 3) bufc = 0;
    }

    // epilogue: bias, target-logit capture, per-thread row max/sumexp
    int   gcol[8];
    float bias[8];
    bool  valid[8];
#pragma unroll
    for (int j = 0; j < 8; j++) {
        int gc = co + ((j < 4) ? ((tx << 2) + j) : (64 + (tx << 2) + j - 4));
        gcol[j] = gc;
        valid[j] = (gc < VOCAB);
        bias[j] = valid[j] ? bd[gc] : 0.0f;
    }
    float m[8], s[8];
#pragma unroll
    for (int i = 0; i < 8; i++) {
        int gr = ro + (ty << 3) + i;
        int tg = tgt[gr];
        float mi = -1e30f;
#pragma unroll
        for (int j = 0; j < 8; j++) {
            float l = valid[j] ? (acc[i][j] + bias[j]) : -1e30f;
            acc[i][j] = l;
            if (valid[j] && gcol[j] == tg) g_lt[gr] = l;
            mi = fmaxf(mi, l);
        }
        float si = 0.0f;
#pragma unroll
        for (int j = 0; j < 8; j++) si += __expf(acc[i][j] - mi);
        m[i] = mi; s[i] = si;
    }

    __syncthreads();   // reuse smem for reduction
    float* redm = sm;          // [128][16]
    float* reds = sm + 2048;   // [128][16]
#pragma unroll
    for (int i = 0; i < 8; i++) {
        redm[((ty << 3) + i) * 16 + tx] = m[i];
        reds[((ty << 3) + i) * 16 + tx] = s[i];
    }
    __syncthreads();
    if (tid < 128) {
        float M = -1e30f;
#pragma unroll
        for (int x = 0; x < 16; x++) M = fmaxf(M, redm[tid * 16 + x]);
        float S = 0.0f;
#pragma unroll
        for (int x = 0; x < 16; x++) S += reds[tid * 16 + x] * __expf(redm[tid * 16 + x] - M);
        g_pmax[blockIdx.x * 4096 + ro + tid] = M;
        g_psum[blockIdx.x * 4096 + ro + tid] = S;
    }
}

// ---------------- kD: combine partials -> perplexity ----------------
__global__ void kD(float* __restrict__ out)
{
    int r = blockIdx.x * 128 + threadIdx.x;   // = b*64 + t
    float M = g_pmax[r];
    float S = g_psum[r];
    for (int i = 1; i < 79; i++) {
        float mi = g_pmax[i * 4096 + r];
        float si = g_psum[i * 4096 + r];
        float nm = fmaxf(M, mi);
        S = S * __expf(M - nm) + si * __expf(mi - nm);
        M = nm;
    }
    out[r] = S * __expf(M - g_lt[r]);   // ppl = sumexp * exp(max - target_logit)
}

// ---------------- launch ----------------
extern "C" void kernel_launch(void* const* d_in, const int* in_sizes, int n_in,
                              void* d_out, int out_size)
{
    const int*   input_data = (const int*)d_in[0];
    const int*   targets    = (const int*)d_in[1];
    const float* E          = (const float*)d_in[2];
    const float* W_lstm     = (const float*)d_in[3];
    const float* b_lstm     = (const float*)d_in[4];
    const float* W_dense    = (const float*)d_in[5];
    const float* b_dense    = (const float*)d_in[6];
    float* out = (float*)d_out;
    (void)in_sizes; (void)n_in; (void)out_size;

    k_init<<<64, 256>>>();
    kA<<<dim3(8, 32), 256>>>(input_data, E, W_lstm, b_lstm);
    kB<<<128, 256>>>(W_lstm);
    kC<<<dim3(79, 32), 256>>>(W_dense, b_dense, targets);
    kD<<<32, 128>>>(out);
}